// round 14
// baseline (speedup 1.0000x reference)
#include <cuda_runtime.h>
#include <cstdint>

// Compressor: per-8x8-block DCT-II (C = M^T B M), per-block inf-norm,
// int8-bin quantization (round-half-even). Quad-lane cooperative blocks:
// lane role c owns input cols {2c,2c+1}; stage-1 column DCT thread-local;
// transpose through per-warp SMEM; stage-2 row DCT thread-local (lane then
// owns rows {2c,2c+1}); quantize; dense coalesced warp stores.
//
// At the HBM mixed-R/W roofline: 516 MB irreducible traffic, DRAM pinned
// 77-79% across all SM-side levers. This round isolates the last free
// variable: default-cache loads (was __ldcs) with streaming stores kept.

static constexpr int W_DIM  = 8192;
static constexpr float RADIUS = 127.0f;
static constexpr float MAGIC  = 12582912.0f;   // 2^23+2^22: RNE rounder, |q|<=127
static constexpr int CTA    = 128;
static constexpr int WARPS  = CTA / 32;

#define C0 0.35355339059327373f
#define C1 0.49039264020161522f
#define C2 0.46193976625564337f
#define C3 0.41573480615127262f
#define C4 0.35355339059327373f
#define C5 0.27778511650980109f
#define C6 0.19134171618254489f
#define C7 0.097545161008064127f

// 8-point orthonormal DCT-II butterfly: out[g] = sum_e M[e][g] * v[e]
#define DCT8(v0,v1,v2,v3,v4,v5,v6,v7, o0,o1,o2,o3,o4,o5,o6,o7)                \
    do {                                                                       \
        const float s0=(v0)+(v7), s1=(v1)+(v6), s2=(v2)+(v5), s3=(v3)+(v4);    \
        const float d0=(v0)-(v7), d1=(v1)-(v6), d2=(v2)-(v5), d3=(v3)-(v4);    \
        const float t0=s0+s3, t1=s1+s2, u0=s0-s3, u1=s1-s2;                    \
        o0 = C0 * (t0 + t1);                                                   \
        o4 = C4 * (t0 - t1);                                                   \
        o2 = fmaf(C2, u0,  C6 * u1);                                           \
        o6 = fmaf(C6, u0, -(C2 * u1));                                         \
        o1 = fmaf( C7, d3, fmaf( C5, d2, fmaf( C3, d1,  C1 * d0)));            \
        o3 = fmaf(-C5, d3, fmaf(-C1, d2, fmaf(-C7, d1,  C3 * d0)));            \
        o5 = fmaf( C3, d3, fmaf( C7, d2, fmaf(-C1, d1,  C5 * d0)));            \
        o7 = fmaf(-C1, d3, fmaf( C3, d2, fmaf(-C5, d1,  C7 * d0)));            \
    } while (0)

__global__ __launch_bounds__(CTA, 10)
void dct_quant_quad_t(const float* __restrict__ x,
                      float* __restrict__ out_indices,
                      float* __restrict__ out_biggest)
{
    __shared__ float2 stage[WARPS * 256];   // 2KB per warp = 8KB

    const int tid  = threadIdx.x;
    const int lane = tid & 31;
    const int wid  = tid >> 5;
    const int b    = lane >> 2;    // block within warp (0..7)
    const int c    = lane & 3;     // role: input cols {2c,2c+1}, later rows {2c,2c+1}

    const int warpBase = blockIdx.x * (WARPS * 8) + wid * 8;
    const int t  = warpBase + b;   // block id
    const int b1 = t >> 10;        // 1024 blocks per row
    const int b2 = t & 1023;

    float2* wbuf  = stage + wid * 256;                    // float2 view
    float4* wbuf4 = reinterpret_cast<float4*>(wbuf);      // float4 view

    // ---- Load cols {2c,2c+1} x 8 rows: 8 float2 loads, warp-dense 256B/row.
    //      Default cache policy (probe: was __ldcs). ----
    const float* src = x + (size_t)(b1 * 8) * W_DIM + (size_t)b2 * 8 + c * 2;
    float A[8][2];
#pragma unroll
    for (int r = 0; r < 8; r++) {
        const float2 v = *reinterpret_cast<const float2*>(src + (size_t)r * W_DIM);
        A[r][0] = v.x; A[r][1] = v.y;
    }

    // ---- Stage 1: thread-local 8-point DCT down each owned column ----
#pragma unroll
    for (int j = 0; j < 2; j++) {
        DCT8(A[0][j],A[1][j],A[2][j],A[3][j],A[4][j],A[5][j],A[6][j],A[7][j],
             A[0][j],A[1][j],A[2][j],A[3][j],A[4][j],A[5][j],A[6][j],A[7][j]);
    }

    // ---- Transpose D through SMEM ----
    // Write: logical float2 slot L = g*4 + c, phys = b*32 + ((L + 4b) & 31)
#pragma unroll
    for (int g = 0; g < 8; g++)
        wbuf[b * 32 + ((g * 4 + c + 4 * b) & 31)] = make_float2(A[g][0], A[g][1]);
    __syncwarp();

    // Read rows r = 2c, 2c+1: float4 L4 = r*2+q, phys = b*16 + ((L4 + 2b) & 15)
    float R[2][8];
#pragma unroll
    for (int q2 = 0; q2 < 2; q2++) {
        const int r = 2 * c + q2;
#pragma unroll
        for (int q = 0; q < 2; q++) {
            const float4 v = wbuf4[b * 16 + ((r * 2 + q + 2 * b) & 15)];
            R[q2][4*q + 0] = v.x; R[q2][4*q + 1] = v.y;
            R[q2][4*q + 2] = v.z; R[q2][4*q + 3] = v.w;
        }
    }

    // ---- Stage 2: thread-local 8-point DCT along each owned row; inf-norm ----
    float maxv = 0.0f;
#pragma unroll
    for (int q2 = 0; q2 < 2; q2++) {
        DCT8(R[q2][0],R[q2][1],R[q2][2],R[q2][3],R[q2][4],R[q2][5],R[q2][6],R[q2][7],
             R[q2][0],R[q2][1],R[q2][2],R[q2][3],R[q2][4],R[q2][5],R[q2][6],R[q2][7]);
#pragma unroll
        for (int j = 0; j < 8; j++) maxv = fmaxf(maxv, fabsf(R[q2][j]));
    }

    // Per-block inf-norm across the quad (lanes 4b..4b+3 hold rows 0-7)
    maxv = fmaxf(maxv, __shfl_xor_sync(0xffffffffu, maxv, 1));
    maxv = fmaxf(maxv, __shfl_xor_sync(0xffffffffu, maxv, 2));
    const float scale = RADIUS / maxv;

    // RNE quantize without converts: (rn(v*scale)+MAGIC)-MAGIC, exact for |q|<=127
#define QUANT(v) (__fadd_rn(__fadd_rn(__fmul_rn((v), scale), MAGIC), -MAGIC))

    __syncwarp();   // all D reads consumed before overwriting the buffer

    // ---- Restage quantized C rows (4 STS.128, same swizzle) ----
#pragma unroll
    for (int q2 = 0; q2 < 2; q2++) {
        const int r = 2 * c + q2;
#pragma unroll
        for (int q = 0; q < 2; q++) {
            float4 v;
            v.x = QUANT(R[q2][4*q + 0]);
            v.y = QUANT(R[q2][4*q + 1]);
            v.z = QUANT(R[q2][4*q + 2]);
            v.w = QUANT(R[q2][4*q + 3]);
            wbuf4[b * 16 + ((r * 2 + q + 2 * b) & 15)] = v;
        }
    }
#undef QUANT
    __syncwarp();

    // ---- Dense 2KB warp store: 4 STG.128 per lane, fully coalesced ----
    float4* gout = reinterpret_cast<float4*>(out_indices) + (size_t)warpBase * 16;
#pragma unroll
    for (int k = 0; k < 4; k++) {
        const int p  = k * 32 + lane;
        const int bb = p >> 4;
        const int f4 = p & 15;
        __stcs(gout + p, wbuf4[bb * 16 + ((f4 + 2 * bb) & 15)]);
    }

    if (c == 0) __stcs(out_biggest + t, maxv);
}

// ---- Fallback (byte-packed int8 output layout) ----
__global__ __launch_bounds__(128)
void dct_quant_i8_kernel(const float* __restrict__ x,
                         int8_t* __restrict__ out_indices,
                         float* __restrict__ out_biggest)
{
    const int t  = blockIdx.x * 128 + threadIdx.x;
    const int b1 = t >> 10;
    const int b2 = t & 1023;
    const float* src = x + (size_t)(b1 * 8) * W_DIM + (size_t)b2 * 8;
    float A[8][8];
#pragma unroll
    for (int e = 0; e < 8; e++) {
        const float4 v0 = __ldcs(reinterpret_cast<const float4*>(src + (size_t)e * W_DIM));
        const float4 v1 = __ldcs(reinterpret_cast<const float4*>(src + (size_t)e * W_DIM + 4));
        A[e][0]=v0.x; A[e][1]=v0.y; A[e][2]=v0.z; A[e][3]=v0.w;
        A[e][4]=v1.x; A[e][5]=v1.y; A[e][6]=v1.z; A[e][7]=v1.w;
    }
#pragma unroll
    for (int f = 0; f < 8; f++) {
        DCT8(A[0][f],A[1][f],A[2][f],A[3][f],A[4][f],A[5][f],A[6][f],A[7][f],
             A[0][f],A[1][f],A[2][f],A[3][f],A[4][f],A[5][f],A[6][f],A[7][f]);
    }
    float maxv = 0.0f;
#pragma unroll
    for (int g = 0; g < 8; g++) {
        DCT8(A[g][0],A[g][1],A[g][2],A[g][3],A[g][4],A[g][5],A[g][6],A[g][7],
             A[g][0],A[g][1],A[g][2],A[g][3],A[g][4],A[g][5],A[g][6],A[g][7]);
#pragma unroll
        for (int j = 0; j < 8; j++) maxv = fmaxf(maxv, fabsf(A[g][j]));
    }
    const float scale = RADIUS / maxv;
    uint32_t words[16];
#pragma unroll
    for (int i = 0; i < 16; i++) {
        const int g = i >> 1, hb = (i & 1) * 4;
        uint32_t w = 0;
#pragma unroll
        for (int j = 0; j < 4; j++) {
            const int q = __float2int_rn(A[g][hb + j] * scale);
            w |= (uint32_t)(q & 0xFF) << (8 * j);
        }
        words[i] = w;
    }
    uint4* outp = reinterpret_cast<uint4*>(out_indices + (size_t)t * 64);
#pragma unroll
    for (int i = 0; i < 4; i++)
        __stcs(outp + i, make_uint4(words[4*i], words[4*i+1], words[4*i+2], words[4*i+3]));
    __stcs(out_biggest + t, maxv);
}

extern "C" void kernel_launch(void* const* d_in, const int* in_sizes, int n_in,
                              void* d_out, int out_size)
{
    const float* x = (const float*)d_in[0];
    // d_in[1] (dct) is the fixed orthonormal DCT-II matrix; baked in as constants.

    const int n       = in_sizes[0];        // 67108864
    const int nblocks = n / 64;             // 1048576

    if (out_size == n + nblocks) {
        float* outF = (float*)d_out;
        const int grid = (nblocks * 4) / CTA;   // 32768
        dct_quant_quad_t<<<grid, CTA>>>(x, outF, outF + n);
    } else {
        int8_t* idx = (int8_t*)d_out;
        float*  big = (float*)((char*)d_out + (size_t)n);
        dct_quant_i8_kernel<<<nblocks / 128, 128>>>(x, idx, big);
    }
}

// round 15
// speedup vs baseline: 1.0082x; 1.0082x over previous
#include <cuda_runtime.h>
#include <cstdint>

// Compressor: per-8x8-block DCT-II (C = M^T B M), per-block inf-norm,
// int8-bin quantization (round-half-even). Quad-lane cooperative blocks:
// lane role c owns input cols {2c,2c+1}; stage-1 column DCT thread-local;
// transpose through per-warp SMEM; stage-2 row DCT thread-local (lane then
// owns rows {2c,2c+1}); quantize; dense coalesced warp stores.
//
// FINAL (converged). HBM mixed-R/W roofline: 516 MB irreducible zero-reuse
// traffic at the measured ~6.27 TB/s R/W-mix ceiling. DRAM utilization is
// invariant at 77-79% across every tested lever: occupancy 22-64%, per-warp
// MLP 2-4KB, L1 pressure 39-78%, instruction count +/-40%, SW pipelining,
// load cache policy. Best-measured config: __launch_bounds__(128,10),
// __ldcs loads, __stcs stores; regs=40, 8KB SMEM; bench 82.0-82.7us.

static constexpr int W_DIM  = 8192;
static constexpr float RADIUS = 127.0f;
static constexpr float MAGIC  = 12582912.0f;   // 2^23+2^22: RNE rounder, |q|<=127
static constexpr int CTA    = 128;
static constexpr int WARPS  = CTA / 32;

#define C0 0.35355339059327373f
#define C1 0.49039264020161522f
#define C2 0.46193976625564337f
#define C3 0.41573480615127262f
#define C4 0.35355339059327373f
#define C5 0.27778511650980109f
#define C6 0.19134171618254489f
#define C7 0.097545161008064127f

// 8-point orthonormal DCT-II butterfly: out[g] = sum_e M[e][g] * v[e]
#define DCT8(v0,v1,v2,v3,v4,v5,v6,v7, o0,o1,o2,o3,o4,o5,o6,o7)                \
    do {                                                                       \
        const float s0=(v0)+(v7), s1=(v1)+(v6), s2=(v2)+(v5), s3=(v3)+(v4);    \
        const float d0=(v0)-(v7), d1=(v1)-(v6), d2=(v2)-(v5), d3=(v3)-(v4);    \
        const float t0=s0+s3, t1=s1+s2, u0=s0-s3, u1=s1-s2;                    \
        o0 = C0 * (t0 + t1);                                                   \
        o4 = C4 * (t0 - t1);                                                   \
        o2 = fmaf(C2, u0,  C6 * u1);                                           \
        o6 = fmaf(C6, u0, -(C2 * u1));                                         \
        o1 = fmaf( C7, d3, fmaf( C5, d2, fmaf( C3, d1,  C1 * d0)));            \
        o3 = fmaf(-C5, d3, fmaf(-C1, d2, fmaf(-C7, d1,  C3 * d0)));            \
        o5 = fmaf( C3, d3, fmaf( C7, d2, fmaf(-C1, d1,  C5 * d0)));            \
        o7 = fmaf(-C1, d3, fmaf( C3, d2, fmaf(-C5, d1,  C7 * d0)));            \
    } while (0)

__global__ __launch_bounds__(CTA, 10)
void dct_quant_quad_t(const float* __restrict__ x,
                      float* __restrict__ out_indices,
                      float* __restrict__ out_biggest)
{
    __shared__ float2 stage[WARPS * 256];   // 2KB per warp = 8KB

    const int tid  = threadIdx.x;
    const int lane = tid & 31;
    const int wid  = tid >> 5;
    const int b    = lane >> 2;    // block within warp (0..7)
    const int c    = lane & 3;     // role: input cols {2c,2c+1}, later rows {2c,2c+1}

    const int warpBase = blockIdx.x * (WARPS * 8) + wid * 8;
    const int t  = warpBase + b;   // block id
    const int b1 = t >> 10;        // 1024 blocks per row
    const int b2 = t & 1023;

    float2* wbuf  = stage + wid * 256;                    // float2 view
    float4* wbuf4 = reinterpret_cast<float4*>(wbuf);      // float4 view

    // ---- Load cols {2c,2c+1} x 8 rows: 8 float2 loads, warp-dense 256B/row ----
    const float* src = x + (size_t)(b1 * 8) * W_DIM + (size_t)b2 * 8 + c * 2;
    float A[8][2];
#pragma unroll
    for (int r = 0; r < 8; r++) {
        const float2 v = __ldcs(reinterpret_cast<const float2*>(src + (size_t)r * W_DIM));
        A[r][0] = v.x; A[r][1] = v.y;
    }

    // ---- Stage 1: thread-local 8-point DCT down each owned column ----
#pragma unroll
    for (int j = 0; j < 2; j++) {
        DCT8(A[0][j],A[1][j],A[2][j],A[3][j],A[4][j],A[5][j],A[6][j],A[7][j],
             A[0][j],A[1][j],A[2][j],A[3][j],A[4][j],A[5][j],A[6][j],A[7][j]);
    }

    // ---- Transpose D through SMEM ----
    // Write: logical float2 slot L = g*4 + c, phys = b*32 + ((L + 4b) & 31)
#pragma unroll
    for (int g = 0; g < 8; g++)
        wbuf[b * 32 + ((g * 4 + c + 4 * b) & 31)] = make_float2(A[g][0], A[g][1]);
    __syncwarp();

    // Read rows r = 2c, 2c+1: float4 L4 = r*2+q, phys = b*16 + ((L4 + 2b) & 15)
    float R[2][8];
#pragma unroll
    for (int q2 = 0; q2 < 2; q2++) {
        const int r = 2 * c + q2;
#pragma unroll
        for (int q = 0; q < 2; q++) {
            const float4 v = wbuf4[b * 16 + ((r * 2 + q + 2 * b) & 15)];
            R[q2][4*q + 0] = v.x; R[q2][4*q + 1] = v.y;
            R[q2][4*q + 2] = v.z; R[q2][4*q + 3] = v.w;
        }
    }

    // ---- Stage 2: thread-local 8-point DCT along each owned row; inf-norm ----
    float maxv = 0.0f;
#pragma unroll
    for (int q2 = 0; q2 < 2; q2++) {
        DCT8(R[q2][0],R[q2][1],R[q2][2],R[q2][3],R[q2][4],R[q2][5],R[q2][6],R[q2][7],
             R[q2][0],R[q2][1],R[q2][2],R[q2][3],R[q2][4],R[q2][5],R[q2][6],R[q2][7]);
#pragma unroll
        for (int j = 0; j < 8; j++) maxv = fmaxf(maxv, fabsf(R[q2][j]));
    }

    // Per-block inf-norm across the quad (lanes 4b..4b+3 hold rows 0-7)
    maxv = fmaxf(maxv, __shfl_xor_sync(0xffffffffu, maxv, 1));
    maxv = fmaxf(maxv, __shfl_xor_sync(0xffffffffu, maxv, 2));
    const float scale = RADIUS / maxv;

    // RNE quantize without converts: (rn(v*scale)+MAGIC)-MAGIC, exact for |q|<=127
#define QUANT(v) (__fadd_rn(__fadd_rn(__fmul_rn((v), scale), MAGIC), -MAGIC))

    __syncwarp();   // all D reads consumed before overwriting the buffer

    // ---- Restage quantized C rows (4 STS.128, same swizzle) ----
#pragma unroll
    for (int q2 = 0; q2 < 2; q2++) {
        const int r = 2 * c + q2;
#pragma unroll
        for (int q = 0; q < 2; q++) {
            float4 v;
            v.x = QUANT(R[q2][4*q + 0]);
            v.y = QUANT(R[q2][4*q + 1]);
            v.z = QUANT(R[q2][4*q + 2]);
            v.w = QUANT(R[q2][4*q + 3]);
            wbuf4[b * 16 + ((r * 2 + q + 2 * b) & 15)] = v;
        }
    }
#undef QUANT
    __syncwarp();

    // ---- Dense 2KB warp store: 4 STG.128 per lane, fully coalesced ----
    float4* gout = reinterpret_cast<float4*>(out_indices) + (size_t)warpBase * 16;
#pragma unroll
    for (int k = 0; k < 4; k++) {
        const int p  = k * 32 + lane;
        const int bb = p >> 4;
        const int f4 = p & 15;
        __stcs(gout + p, wbuf4[bb * 16 + ((f4 + 2 * bb) & 15)]);
    }

    if (c == 0) __stcs(out_biggest + t, maxv);
}

// ---- Fallback (byte-packed int8 output layout) ----
__global__ __launch_bounds__(128)
void dct_quant_i8_kernel(const float* __restrict__ x,
                         int8_t* __restrict__ out_indices,
                         float* __restrict__ out_biggest)
{
    const int t  = blockIdx.x * 128 + threadIdx.x;
    const int b1 = t >> 10;
    const int b2 = t & 1023;
    const float* src = x + (size_t)(b1 * 8) * W_DIM + (size_t)b2 * 8;
    float A[8][8];
#pragma unroll
    for (int e = 0; e < 8; e++) {
        const float4 v0 = __ldcs(reinterpret_cast<const float4*>(src + (size_t)e * W_DIM));
        const float4 v1 = __ldcs(reinterpret_cast<const float4*>(src + (size_t)e * W_DIM + 4));
        A[e][0]=v0.x; A[e][1]=v0.y; A[e][2]=v0.z; A[e][3]=v0.w;
        A[e][4]=v1.x; A[e][5]=v1.y; A[e][6]=v1.z; A[e][7]=v1.w;
    }
#pragma unroll
    for (int f = 0; f < 8; f++) {
        DCT8(A[0][f],A[1][f],A[2][f],A[3][f],A[4][f],A[5][f],A[6][f],A[7][f],
             A[0][f],A[1][f],A[2][f],A[3][f],A[4][f],A[5][f],A[6][f],A[7][f]);
    }
    float maxv = 0.0f;
#pragma unroll
    for (int g = 0; g < 8; g++) {
        DCT8(A[g][0],A[g][1],A[g][2],A[g][3],A[g][4],A[g][5],A[g][6],A[g][7],
             A[g][0],A[g][1],A[g][2],A[g][3],A[g][4],A[g][5],A[g][6],A[g][7]);
#pragma unroll
        for (int j = 0; j < 8; j++) maxv = fmaxf(maxv, fabsf(A[g][j]));
    }
    const float scale = RADIUS / maxv;
    uint32_t words[16];
#pragma unroll
    for (int i = 0; i < 16; i++) {
        const int g = i >> 1, hb = (i & 1) * 4;
        uint32_t w = 0;
#pragma unroll
        for (int j = 0; j < 4; j++) {
            const int q = __float2int_rn(A[g][hb + j] * scale);
            w |= (uint32_t)(q & 0xFF) << (8 * j);
        }
        words[i] = w;
    }
    uint4* outp = reinterpret_cast<uint4*>(out_indices + (size_t)t * 64);
#pragma unroll
    for (int i = 0; i < 4; i++)
        __stcs(outp + i, make_uint4(words[4*i], words[4*i+1], words[4*i+2], words[4*i+3]));
    __stcs(out_biggest + t, maxv);
}

extern "C" void kernel_launch(void* const* d_in, const int* in_sizes, int n_in,
                              void* d_out, int out_size)
{
    const float* x = (const float*)d_in[0];
    // d_in[1] (dct) is the fixed orthonormal DCT-II matrix; baked in as constants.

    const int n       = in_sizes[0];        // 67108864
    const int nblocks = n / 64;             // 1048576

    if (out_size == n + nblocks) {
        float* outF = (float*)d_out;
        const int grid = (nblocks * 4) / CTA;   // 32768
        dct_quant_quad_t<<<grid, CTA>>>(x, outF, outF + n);
    } else {
        int8_t* idx = (int8_t*)d_out;
        float*  big = (float*)((char*)d_out + (size_t)n);
        dct_quant_i8_kernel<<<nblocks / 128, 128>>>(x, idx, big);
    }
}